// round 12
// baseline (speedup 1.0000x reference)
#include <cuda_runtime.h>
#include <cstdint>

// E2M1 block quantizer — software bit-trick encode, streaming-hint I/O.
// One thread = 8 contiguous elements; 4 lanes share a 32-element quant block.
// Output layout (float32, reference-tuple order):
//   [0, n)          deq_weight
//   [n, 2n)         encoded (0..15)
//   [2n, 2n+nb)     e8m0 scale + 127
//   [2n+nb, 2n+2nb) eps_base = 0.5*tanh(eps_param)

__global__ __launch_bounds__(256) void e2m1_quant_kernel(
    const float* __restrict__ w,
    const float* __restrict__ eps_param,
    float* __restrict__ deq,
    float* __restrict__ enc,
    float* __restrict__ scl,
    float* __restrict__ epsb,
    int n_elem)
{
    const int t = blockIdx.x * blockDim.x + threadIdx.x;
    const long base = (long)t * 8;
    if (base >= (long)n_elem) return;

    const int blk = t >> 2;  // 32-element quant block (4 threads/block)

    // front-batched independent 128-bit streaming loads (MLP=2 per thread)
    const float4 w0 = __ldcs(reinterpret_cast<const float4*>(w + base));
    const float4 w1 = __ldcs(reinterpret_cast<const float4*>(w + base + 4));

    // ---- block amax: FMNMX |.| tree + 2 butterfly levels ----
    float am = fmaxf(fmaxf(fmaxf(fabsf(w0.x), fabsf(w0.y)),
                           fmaxf(fabsf(w0.z), fabsf(w0.w))),
                     fmaxf(fmaxf(fabsf(w1.x), fabsf(w1.y)),
                           fmaxf(fabsf(w1.z), fabsf(w1.w))));
    am = fmaxf(am, __shfl_xor_sync(0xffffffffu, am, 1));
    am = fmaxf(am, __shfl_xor_sync(0xffffffffu, am, 2));

    // ---- e8m0: k = e8+127 = exp_field(descale) + (frac != 0)  (== ceil(log2)) ----
    const float descale = am * 0.16666667f;  // 1/6
    const unsigned db = __float_as_uint(descale);
    const int k = (int)(db >> 23) + ((db & 0x7FFFFFu) ? 1 : 0);  // db==0 -> k=0
    const float scale     = __uint_as_float((unsigned)k << 23);
    const float inv_scale = __uint_as_float((unsigned)(254 - k) << 23);

    // ---- block epsilon: fast tanh via MUFU.EX2 (~2e-7 rel) ----
    const float et = __expf(2.0f * eps_param[blk]);
    const float eps = 0.5f * (et - 1.0f) * __fdividef(1.0f, et + 1.0f);

    // ---- per-element encode + dequant ----
    float dq[8], ef[8];
    const float win[8] = {w0.x, w0.y, w0.z, w0.w, w1.x, w1.y, w1.z, w1.w};
    #pragma unroll
    for (int i = 0; i < 8; i++) {
        const float a = win[i];
        // s = max(|a|*2^-e8 + eps, 0); pow2 multiply exact -> FFMA == ref two-step
        const float s = fmaxf(fmaf(fabsf(a), inv_scale, eps), 0.0f);

        // normal region: clamp to [1,6], round to 1 mantissa bit (grid 1,1.5,2,3,4,6;
        // midpoint thresholds 1.25/1.75/2.5/3.5/5 match the reference bounds)
        const float sc = fminf(fmaxf(s, 1.0f), 6.0f);
        const unsigned r = (__float_as_uint(sc) + 0x00200000u) & 0xFFC00000u;

        const bool pbig = (s > 0.75f);   // -> q >= 1
        const bool psml = (s > 0.25f);   // -> q = 0.5 in sub-1 region

        const unsigned qb = pbig ? r : (psml ? 0x3F000000u : 0u);
        const int ord = pbig ? ((int)(r >> 22) - 252) : (psml ? 1 : 0);

        const bool pneg = !(a > 0.0f);   // matches floor((2-sign)/2), incl. zero
        ef[i] = (float)(pneg ? ord + 8 : ord);

        const float dv = __uint_as_float(qb) * scale;  // exact pow2 scaling
        dq[i] = pneg ? -dv : dv;
    }

    // streaming 128-bit stores (write-once data, evict-first)
    __stcs(reinterpret_cast<float4*>(deq + base),
           make_float4(dq[0], dq[1], dq[2], dq[3]));
    __stcs(reinterpret_cast<float4*>(deq + base + 4),
           make_float4(dq[4], dq[5], dq[6], dq[7]));
    if (enc) {
        __stcs(reinterpret_cast<float4*>(enc + base),
               make_float4(ef[0], ef[1], ef[2], ef[3]));
        __stcs(reinterpret_cast<float4*>(enc + base + 4),
               make_float4(ef[4], ef[5], ef[6], ef[7]));
    }

    if ((t & 3) == 0 && scl) {
        __stcs(scl + blk,  (float)k);
        __stcs(epsb + blk, eps);
    }
}

extern "C" void kernel_launch(void* const* d_in, const int* in_sizes, int n_in,
                              void* d_out, int out_size) {
    const float* w  = (const float*)d_in[0];   // weight_fp [out_f*in_f]
    const float* ep = (const float*)d_in[1];   // eps_param [out_f*in_f/32]
    const int n  = in_sizes[0];
    const int nb = (n_in > 1) ? in_sizes[1] : n / 32;

    float* out  = (float*)d_out;
    float* deq  = out;
    float* enc  = nullptr;
    float* scl  = nullptr;
    float* epsb = nullptr;

    const long total_all = 2L * n + 2L * nb;
    if ((long)out_size >= total_all) {
        enc  = out + n;
        scl  = out + 2L * n;
        epsb = scl + nb;
    } else if ((long)out_size >= 2L * n) {
        enc = out + n;
    }

    const int threads = 256;
    const int nthreads_total = n / 8;
    const int ctas = (nthreads_total + threads - 1) / threads;
    e2m1_quant_kernel<<<ctas, threads>>>(w, ep, deq, enc, scl, epsb, n);
}

// round 13
// speedup vs baseline: 1.0010x; 1.0010x over previous
#include <cuda_runtime.h>
#include <cstdint>

// E2M1 block quantizer — 256-bit vector I/O (LDG.E.256/STG.E.256, sm_100+).
// One thread = 16 contiguous elements; 2 lanes share a 32-element quant block.
// Output layout (float32, reference-tuple order):
//   [0, n)          deq_weight
//   [n, 2n)         encoded (0..15)
//   [2n, 2n+nb)     e8m0 scale + 127
//   [2n+nb, 2n+2nb) eps_base = 0.5*tanh(eps_param)

__device__ __forceinline__ void ldg256_cs(const float* p, float* v) {
    asm("ld.global.cs.v8.f32 {%0,%1,%2,%3,%4,%5,%6,%7}, [%8];"
        : "=f"(v[0]), "=f"(v[1]), "=f"(v[2]), "=f"(v[3]),
          "=f"(v[4]), "=f"(v[5]), "=f"(v[6]), "=f"(v[7])
        : "l"(p));
}

__device__ __forceinline__ void stg256_cs(float* p, const float* v) {
    asm volatile("st.global.cs.v8.f32 [%0], {%1,%2,%3,%4,%5,%6,%7,%8};"
        :: "l"(p),
           "f"(v[0]), "f"(v[1]), "f"(v[2]), "f"(v[3]),
           "f"(v[4]), "f"(v[5]), "f"(v[6]), "f"(v[7])
        : "memory");
}

__global__ __launch_bounds__(256) void e2m1_quant_kernel(
    const float* __restrict__ w,
    const float* __restrict__ eps_param,
    float* __restrict__ deq,
    float* __restrict__ enc,
    float* __restrict__ scl,
    float* __restrict__ epsb,
    int n_elem)
{
    const int t = blockIdx.x * blockDim.x + threadIdx.x;
    const long base = (long)t * 16;
    if (base >= (long)n_elem) return;

    const int blk = t >> 1;  // 32-element quant block (2 threads/block)

    // two independent 256-bit streaming loads, front-batched (MLP_p1 = 2)
    float win[16];
    ldg256_cs(w + base,     win);
    ldg256_cs(w + base + 8, win + 8);

    // ---- block amax: FMNMX |.| tree (15 ops) + 1 butterfly level ----
    float am = fabsf(win[0]);
    #pragma unroll
    for (int i = 1; i < 16; i++) am = fmaxf(am, fabsf(win[i]));
    am = fmaxf(am, __shfl_xor_sync(0xffffffffu, am, 1));

    // ---- e8m0: k = e8+127 = exp_field(descale) + (frac != 0)  (== ceil(log2)) ----
    const float descale = am * 0.16666667f;  // 1/6
    const unsigned db = __float_as_uint(descale);
    const int k = (int)(db >> 23) + ((db & 0x7FFFFFu) ? 1 : 0);  // db==0 -> k=0
    const float scale     = __uint_as_float((unsigned)k << 23);
    const float inv_scale = __uint_as_float((unsigned)(254 - k) << 23);

    // ---- block epsilon: fast tanh via MUFU.EX2 (~2e-7 rel) ----
    const float et = __expf(2.0f * eps_param[blk]);
    const float eps = 0.5f * (et - 1.0f) * __fdividef(1.0f, et + 1.0f);

    // ---- per-element encode + dequant ----
    float dq[16], ef[16];
    #pragma unroll
    for (int i = 0; i < 16; i++) {
        const float a = win[i];
        // s = max(|a|*2^-e8 + eps, 0); pow2 multiply exact -> FFMA == ref two-step
        const float s = fmaxf(fmaf(fabsf(a), inv_scale, eps), 0.0f);

        // normal region: clamp to [1,6], round to 1 mantissa bit (grid 1,1.5,2,3,4,6;
        // midpoint thresholds 1.25/1.75/2.5/3.5/5 match the reference bounds)
        const float sc = fminf(fmaxf(s, 1.0f), 6.0f);
        const unsigned r = (__float_as_uint(sc) + 0x00200000u) & 0xFFC00000u;

        const bool pbig = (s > 0.75f);   // -> q >= 1
        const bool psml = (s > 0.25f);   // -> q = 0.5 in sub-1 region

        const unsigned qb = pbig ? r : (psml ? 0x3F000000u : 0u);
        const int ord = pbig ? ((int)(r >> 22) - 252) : (psml ? 1 : 0);

        const bool pneg = !(a > 0.0f);   // matches floor((2-sign)/2), incl. zero
        ef[i] = (float)(pneg ? ord + 8 : ord);

        const float dv = __uint_as_float(qb) * scale;  // exact pow2 scaling
        dq[i] = pneg ? -dv : dv;
    }

    // 256-bit streaming stores (write-once data, evict-first)
    stg256_cs(deq + base,     dq);
    stg256_cs(deq + base + 8, dq + 8);
    if (enc) {
        stg256_cs(enc + base,     ef);
        stg256_cs(enc + base + 8, ef + 8);
    }

    if ((t & 1) == 0 && scl) {
        __stcs(scl + blk,  (float)k);
        __stcs(epsb + blk, eps);
    }
}

extern "C" void kernel_launch(void* const* d_in, const int* in_sizes, int n_in,
                              void* d_out, int out_size) {
    const float* w  = (const float*)d_in[0];   // weight_fp [out_f*in_f]
    const float* ep = (const float*)d_in[1];   // eps_param [out_f*in_f/32]
    const int n  = in_sizes[0];
    const int nb = (n_in > 1) ? in_sizes[1] : n / 32;

    float* out  = (float*)d_out;
    float* deq  = out;
    float* enc  = nullptr;
    float* scl  = nullptr;
    float* epsb = nullptr;

    const long total_all = 2L * n + 2L * nb;
    if ((long)out_size >= total_all) {
        enc  = out + n;
        scl  = out + 2L * n;
        epsb = scl + nb;
    } else if ((long)out_size >= 2L * n) {
        enc = out + n;
    }

    const int threads = 256;
    const int nthreads_total = n / 16;
    const int ctas = (nthreads_total + threads - 1) / threads;
    e2m1_quant_kernel<<<ctas, threads>>>(w, ep, deq, enc, scl, epsb, n);
}